// round 3
// baseline (speedup 1.0000x reference)
#include <cuda_runtime.h>

// ---------------------------------------------------------------------------
// pcqmPostProcess:
//   x          [N_LG, D]  f32
//   lg_node_idx[N_LG, 2]  i32  (local original-node indices)
//   ptr        [B+1]      i32  (line-graph CSR offsets)
//   org_graph_size [B]    i32
//   edge_label_size[B]    i32
//   edge_index_labeled [2, E] i32
// Outputs (flattened, concatenated, as f32):
//   x_new [N, D], edge_index_labeled_new [2, E], ptr_new [B+1], batch_vec [N]
// ---------------------------------------------------------------------------

#define MAX_B 8192
__device__ int g_node_off[MAX_B + 1];   // exclusive cumsum of org_graph_size (incl. total at [B])
__device__ int g_edge_off[MAX_B + 1];   // exclusive cumsum of edge_label_size

// ---------------------------------------------------------------------------
// Single-block dual Hillis-Steele scan (tiles of 2048, carry across tiles).
// ---------------------------------------------------------------------------
__global__ void scan_kernel(const int* __restrict__ gs, const int* __restrict__ es, int B) {
    __shared__ int s[2048];
    __shared__ int t[2048];
    int tid = threadIdx.x;           // 0..1023
    int carry_g = 0, carry_e = 0;
    if (tid == 0) { g_node_off[0] = 0; g_edge_off[0] = 0; }

    for (int base = 0; base < B; base += 2048) {
        int i0 = base + tid;
        int i1 = base + tid + 1024;
        s[tid]        = (i0 < B) ? gs[i0] : 0;
        s[tid + 1024] = (i1 < B) ? gs[i1] : 0;
        t[tid]        = (i0 < B) ? es[i0] : 0;
        t[tid + 1024] = (i1 < B) ? es[i1] : 0;
        __syncthreads();

        for (int d = 1; d < 2048; d <<= 1) {
            int a0 = 0, a1 = 0, b0 = 0, b1 = 0;
            if (tid >= d)        { a0 = s[tid - d];        b0 = t[tid - d]; }
            if (tid + 1024 >= d) { a1 = s[tid + 1024 - d]; b1 = t[tid + 1024 - d]; }
            __syncthreads();
            s[tid]        += a0;  t[tid]        += b0;
            s[tid + 1024] += a1;  t[tid + 1024] += b1;
            __syncthreads();
        }

        if (i0 < B) { g_node_off[i0 + 1] = s[tid] + carry_g;
                      g_edge_off[i0 + 1] = t[tid] + carry_e; }
        if (i1 < B) { g_node_off[i1 + 1] = s[tid + 1024] + carry_g;
                      g_edge_off[i1 + 1] = t[tid + 1024] + carry_e; }
        __syncthreads();
        carry_g += s[2047];
        carry_e += t[2047];
        __syncthreads();
    }
}

// ---------------------------------------------------------------------------
// One CTA per graph. Thread c owns column c. Each row j of this graph's
// line-graph slice contributes x[j, 0:hd2] to incoming[dst] (idx col 1) and
// x[j, hd2:D] to outgoing[src] (idx col 0). Since each output column needs
// exactly one of the two means, a single fused accumulation buffer suffices:
// column c accumulates into node sidx[2*j + (c < hd2 ? 1 : 0)].
// Conflict-free non-atomic smem accumulation, then mean + coalesced write.
// ---------------------------------------------------------------------------
#define MAX_NODES 32
#define ROW_CHUNK 128

__global__ void __launch_bounds__(320)
fuse_kernel(const float* __restrict__ x, const int* __restrict__ lgidx,
            const int* __restrict__ ptr, const int* __restrict__ gsize,
            float* __restrict__ xnew, int D, int hd2) {
    extern __shared__ char smem_raw[];
    float* accum = (float*)smem_raw;                              // MAX_NODES * D
    int*   cin   = (int*)(smem_raw + (size_t)MAX_NODES * D * 4);  // MAX_NODES
    int*   cout_ = cin + MAX_NODES;                               // MAX_NODES
    int*   sidx  = cout_ + MAX_NODES;                             // 2 * ROW_CHUNK

    int b    = blockIdx.x;
    int nn   = min(gsize[b], MAX_NODES);
    int noff = g_node_off[b];
    int r0 = ptr[b], r1 = ptr[b + 1];
    int tid = threadIdx.x;

    for (int i = tid; i < nn * D; i += blockDim.x) accum[i] = 0.0f;
    if (tid < 2 * MAX_NODES) cin[tid] = 0;
    __syncthreads();

    for (int cs = r0; cs < r1; cs += ROW_CHUNK) {
        int nr = min(ROW_CHUNK, r1 - cs);
        for (int i = tid; i < 2 * nr; i += blockDim.x)
            sidx[i] = lgidx[2 * (size_t)cs + i] & (MAX_NODES - 1);
        __syncthreads();

        if (tid < nr) {
            atomicAdd(&cout_[sidx[2 * tid]],     1);  // idx col 0 -> outgoing src
            atomicAdd(&cin  [sidx[2 * tid + 1]], 1);  // idx col 1 -> incoming dst
        }
        if (tid < D) {
            int sel = (tid < hd2) ? 1 : 0;            // incoming half uses idx col 1
            const float* xp = x + (size_t)cs * D + tid;
            #pragma unroll 5
            for (int j = 0; j < nr; j++) {
                int u = sidx[2 * j + sel];
                accum[u * D + tid] += xp[(size_t)j * D];
            }
        }
        __syncthreads();
    }

    // mean + write (coalesced)
    float* dst = xnew + (size_t)noff * D;
    for (int i = tid; i < nn * D; i += blockDim.x) {
        int u = i / D, c = i - u * D;
        int cnt = (c < hd2) ? cin[u] : cout_[u];
        dst[i] = (cnt > 0) ? accum[i] / (float)cnt : 0.0f;
    }
}

// ---------------------------------------------------------------------------
// Small outputs: edge_index_labeled_new, ptr_new, batch_vec (all as f32).
// ---------------------------------------------------------------------------
__global__ void misc_kernel(const int* __restrict__ ptr, const int* __restrict__ eidx,
                            float* __restrict__ out, int B, int E, int N,
                            size_t off_e) {
    int i = blockIdx.x * blockDim.x + threadIdx.x;
    int two_e = 2 * E;
    size_t off_p = off_e + two_e;
    size_t off_b = off_p + B + 1;

    if (i < two_e) {
        int e = i % E;
        // find g: g_edge_off[g] <= e < g_edge_off[g+1]
        int lo = 0, hi = B;
        while (hi - lo > 1) {
            int mid = (lo + hi) >> 1;
            if (g_edge_off[mid] <= e) lo = mid; else hi = mid;
        }
        int lg_off = ptr[lo] - ptr[0];
        out[off_e + i] = (float)(eidx[i] - lg_off);
    } else if (i < two_e + (B + 1)) {
        int k = i - two_e;
        out[off_p + k] = (float)g_node_off[k];
    } else {
        int n = i - two_e - (B + 1);
        if (n < N) {
            int lo = 0, hi = B;
            while (hi - lo > 1) {
                int mid = (lo + hi) >> 1;
                if (g_node_off[mid] <= n) lo = mid; else hi = mid;
            }
            out[off_b + n] = (float)lo;
        }
    }
}

extern "C" void kernel_launch(void* const* d_in, const int* in_sizes, int n_in,
                              void* d_out, int out_size) {
    const float* x     = (const float*)d_in[0];
    const int*   lgidx = (const int*)d_in[1];
    const int*   ptr   = (const int*)d_in[2];
    const int*   gsize = (const int*)d_in[3];
    const int*   esize = (const int*)d_in[4];
    const int*   eidx  = (const int*)d_in[5];

    int n_lg = in_sizes[1] / 2;
    int D    = in_sizes[0] / n_lg;          // 300
    int B    = in_sizes[2] - 1;             // from ptr length (robust)
    int E    = in_sizes[5] / 2;
    int N    = (out_size - 2 * E - (B + 1)) / (D + 1);
    int hd2  = 2 * (D / 3);                 // 200

    float* out = (float*)d_out;

    scan_kernel<<<1, 1024>>>(gsize, esize, B);

    size_t smem = (size_t)MAX_NODES * D * 4 + 2 * MAX_NODES * 4 + 2 * ROW_CHUNK * 4;
    fuse_kernel<<<B, 320, smem>>>(x, lgidx, ptr, gsize, out, D, hd2);

    size_t off_e = (size_t)N * D;
    int total = 2 * E + (B + 1) + N;
    misc_kernel<<<(total + 255) / 256, 256>>>(ptr, eidx, out, B, E, N, off_e);
}